// round 1
// baseline (speedup 1.0000x reference)
#include <cuda_runtime.h>
#include <cuda_bf16.h>
#include <cstdint>
#include <cstddef>

// Problem constants
// B=4, T=2048, C=1024, H=16, D=64
#define NB 4
#define NT 2048
#define NC 1024
#define NH 16
#define ND 64

// Head-major scratch [B,H,T,D] for q,k,v; attention output in [B,T,C] for proj GEMM.
__device__ float g_q[(size_t)NB * NH * NT * ND];
__device__ float g_k[(size_t)NB * NH * NT * ND];
__device__ float g_v[(size_t)NB * NH * NT * ND];
__device__ float g_ao[(size_t)NB * NT * NC];

__device__ __forceinline__ float ftf32(float x) {
    unsigned u;
    asm("cvt.rna.tf32.f32 %0, %1;" : "=r"(u) : "f"(x));
    return __uint_as_float(u);
}

__device__ __forceinline__ void mma8(float* c, const unsigned* a, const unsigned* b) {
    asm volatile(
        "mma.sync.aligned.m16n8k8.row.col.f32.tf32.tf32.f32 "
        "{%0,%1,%2,%3}, {%4,%5,%6,%7}, {%8,%9}, {%0,%1,%2,%3};\n"
        : "+f"(c[0]), "+f"(c[1]), "+f"(c[2]), "+f"(c[3])
        : "r"(a[0]), "r"(a[1]), "r"(a[2]), "r"(a[3]), "r"(b[0]), "r"(b[1]));
}

// Scatter epilogue for the QKV GEMM: col in [0,3072) -> (s, h, d); row -> (b, t).
// q is pre-scaled by 1/sqrt(D) = 0.125.
__device__ __forceinline__ void scatter_qkv(int gm, int gc, float v) {
    int s = gc >> 10;
    int rem = gc & 1023;
    int h = rem >> 6;
    int d = rem & 63;
    int b = gm >> 11;
    int t = gm & 2047;
    size_t idx = (((size_t)(b * NH + h)) * NT + t) * ND + d;
    if (s == 0)      g_q[idx] = v * 0.125f;
    else if (s == 1) g_k[idx] = v;
    else             g_v[idx] = v;
}

// ---------------------------------------------------------------------------
// TF32 GEMM: C[M x N] = A[M x K] * B[K x N], both row-major fp32.
// Block tile 128x128, K-tile 16, double-buffered smem, 8 warps (2x4 warp grid),
// warp tile 64x32, mma m16n8k8.
// EPI: 0 = plain store to Cout, 1 = scatter into g_q/g_k/g_v.
// ASRC: 0 = A param, 1 = A is g_ao (attention output).
// ---------------------------------------------------------------------------
template <int N, int K, int EPI, int ASRC>
__global__ __launch_bounds__(256, 2)
void gemm_tf32(const float* __restrict__ A, const float* __restrict__ Bm,
               float* __restrict__ Cout) {
    __shared__ float As[2][128][20];   // pitch 20: frag reads conflict-free
    __shared__ float Bs[2][16][136];   // pitch 136: frag reads conflict-free

    const int tid = threadIdx.x;
    const int lane = tid & 31, warp = tid >> 5;
    const int wm = warp & 1, wn = warp >> 1;
    const int quad = lane >> 2, qid = lane & 3;
    const int bm = blockIdx.y * 128, bn = blockIdx.x * 128;

    const float* Ap = ASRC ? (const float*)g_ao : A;

    // gmem load mapping
    const int ar = tid >> 1;            // A row within tile (0..127)
    const int ac = (tid & 1) * 8;       // A col base (0 or 8)
    const int br = tid >> 5;            // B row (0..7), also br+8
    const int bc = (tid & 31) * 4;      // B col base

    float acc[4][4][4];
#pragma unroll
    for (int i = 0; i < 4; i++)
#pragma unroll
        for (int j = 0; j < 4; j++)
#pragma unroll
            for (int k = 0; k < 4; k++) acc[i][j][k] = 0.f;

    float4 ra0, ra1, rb0, rb1;
    const int nk = K / 16;

#define LOADG(kt_)                                                             \
    {                                                                          \
        const float* ap_ = Ap + (size_t)(bm + ar) * K + (kt_) * 16 + ac;       \
        ra0 = *(const float4*)ap_;                                             \
        ra1 = *(const float4*)(ap_ + 4);                                       \
        const float* bp_ = Bm + (size_t)((kt_) * 16 + br) * N + bn + bc;       \
        rb0 = *(const float4*)bp_;                                             \
        rb1 = *(const float4*)(bp_ + (size_t)8 * N);                           \
    }

#define STORES(bb_)                                                            \
    {                                                                          \
        float* a0_ = &As[bb_][ar][ac];                                         \
        a0_[0] = ftf32(ra0.x); a0_[1] = ftf32(ra0.y);                          \
        a0_[2] = ftf32(ra0.z); a0_[3] = ftf32(ra0.w);                          \
        a0_[4] = ftf32(ra1.x); a0_[5] = ftf32(ra1.y);                          \
        a0_[6] = ftf32(ra1.z); a0_[7] = ftf32(ra1.w);                          \
        float* b0_ = &Bs[bb_][br][bc];                                         \
        b0_[0] = ftf32(rb0.x); b0_[1] = ftf32(rb0.y);                          \
        b0_[2] = ftf32(rb0.z); b0_[3] = ftf32(rb0.w);                          \
        float* b1_ = &Bs[bb_][br + 8][bc];                                     \
        b1_[0] = ftf32(rb1.x); b1_[1] = ftf32(rb1.y);                          \
        b1_[2] = ftf32(rb1.z); b1_[3] = ftf32(rb1.w);                          \
    }

    LOADG(0);
    STORES(0);
    __syncthreads();

    for (int kt = 0; kt < nk; kt++) {
        const int bb = kt & 1;
        const bool more = (kt + 1 < nk);
        if (more) LOADG(kt + 1);

#pragma unroll
        for (int kb = 0; kb < 16; kb += 8) {
            unsigned af[4][4], bf[4][2];
#pragma unroll
            for (int mt = 0; mt < 4; mt++) {
                int r = wm * 64 + mt * 16 + quad;
                af[mt][0] = __float_as_uint(As[bb][r][kb + qid]);
                af[mt][1] = __float_as_uint(As[bb][r + 8][kb + qid]);
                af[mt][2] = __float_as_uint(As[bb][r][kb + qid + 4]);
                af[mt][3] = __float_as_uint(As[bb][r + 8][kb + qid + 4]);
            }
#pragma unroll
            for (int nt = 0; nt < 4; nt++) {
                int cn = wn * 32 + nt * 8 + quad;
                bf[nt][0] = __float_as_uint(Bs[bb][kb + qid][cn]);
                bf[nt][1] = __float_as_uint(Bs[bb][kb + qid + 4][cn]);
            }
#pragma unroll
            for (int mt = 0; mt < 4; mt++)
#pragma unroll
                for (int nt = 0; nt < 4; nt++)
                    mma8(acc[mt][nt], af[mt], bf[nt]);
        }

        if (more) STORES(bb ^ 1);
        __syncthreads();
    }
#undef LOADG
#undef STORES

    // Epilogue
#pragma unroll
    for (int mt = 0; mt < 4; mt++) {
        int r0 = bm + wm * 64 + mt * 16 + quad;
#pragma unroll
        for (int nt = 0; nt < 4; nt++) {
            int c0 = bn + wn * 32 + nt * 8 + 2 * qid;
            float* cc = acc[mt][nt];
            if constexpr (EPI == 0) {
                Cout[(size_t)r0 * N + c0] = cc[0];
                Cout[(size_t)r0 * N + c0 + 1] = cc[1];
                Cout[(size_t)(r0 + 8) * N + c0] = cc[2];
                Cout[(size_t)(r0 + 8) * N + c0 + 1] = cc[3];
            } else {
                scatter_qkv(r0, c0, cc[0]);
                scatter_qkv(r0, c0 + 1, cc[1]);
                scatter_qkv(r0 + 8, c0, cc[2]);
                scatter_qkv(r0 + 8, c0 + 1, cc[3]);
            }
        }
    }
}

// ---------------------------------------------------------------------------
// Flash attention (causal, online softmax), fp32 SIMT.
// Grid: (T/64, B*H). Block: 256 threads. q-tile 64 rows, k-tile 32 keys.
// Thread (tx = tid&7, ty = tid>>3) owns q rows {2ty, 2ty+1} and
// output/key columns {tx + 8c : c in 0..}.
// Q is pre-scaled by 1/sqrt(D) at scatter time.
// ---------------------------------------------------------------------------
__global__ __launch_bounds__(256)
void attn_kernel() {
    const int qt = blockIdx.x;     // q tile (0..31)
    const int bh = blockIdx.y;     // b*H + h (0..63)
    const int b = bh >> 4, h = bh & 15;

    __shared__ float Qs[64][64];   // broadcast reads -> no pad needed
    __shared__ float Ks[32][68];   // pitch 68: strided-col float4 reads conflict-free
    __shared__ float Vt[64][36];   // V transposed: [d][k], pitch 36
    __shared__ float Ps[64][36];   // probabilities: [row][k], pitch 36

    const int tid = threadIdx.x;
    const int tx = tid & 7;
    const int ty = tid >> 3;       // 0..31

    const float* Qg = g_q + ((size_t)bh * NT + (size_t)qt * 64) * ND;
    const float* Kg = g_k + (size_t)bh * NT * ND;
    const float* Vg = g_v + (size_t)bh * NT * ND;

    // Load Q tile (4096 floats)
#pragma unroll
    for (int i = 0; i < 4; i++) {
        int idx = tid + i * 256;
        int r = idx >> 4, c4 = (idx & 15) * 4;
        *(float4*)&Qs[r][c4] = *(const float4*)&Qg[r * 64 + c4];
    }

    float m_[2] = {-1e30f, -1e30f};
    float l_[2] = {0.f, 0.f};
    float acc[2][8];
#pragma unroll
    for (int r = 0; r < 2; r++)
#pragma unroll
        for (int c = 0; c < 8; c++) acc[r][c] = 0.f;

    const int nkt = 2 * qt + 2;    // causal: only tiles up to the diagonal
    for (int kt = 0; kt < nkt; kt++) {
        const float* kp = Kg + (size_t)kt * 32 * 64;
        const float* vp = Vg + (size_t)kt * 32 * 64;
#pragma unroll
        for (int i = 0; i < 2; i++) {
            int idx = tid + i * 256;
            int r = idx >> 4, c4 = (idx & 15) * 4;
            float4 kv = *(const float4*)&kp[r * 64 + c4];
            *(float4*)&Ks[r][c4] = kv;
            float4 vv = *(const float4*)&vp[r * 64 + c4];
            Vt[c4 + 0][r] = vv.x;
            Vt[c4 + 1][r] = vv.y;
            Vt[c4 + 2][r] = vv.z;
            Vt[c4 + 3][r] = vv.w;
        }
        __syncthreads();

        // S = Q K^T  (cols tx + 8c)
        float s0[4] = {0.f, 0.f, 0.f, 0.f};
        float s1[4] = {0.f, 0.f, 0.f, 0.f};
#pragma unroll
        for (int d4 = 0; d4 < 64; d4 += 4) {
            float4 q0 = *(float4*)&Qs[2 * ty + 0][d4];
            float4 q1 = *(float4*)&Qs[2 * ty + 1][d4];
#pragma unroll
            for (int c = 0; c < 4; c++) {
                float4 kk = *(float4*)&Ks[tx + 8 * c][d4];
                s0[c] += q0.x * kk.x + q0.y * kk.y + q0.z * kk.z + q0.w * kk.w;
                s1[c] += q1.x * kk.x + q1.y * kk.y + q1.z * kk.z + q1.w * kk.w;
            }
        }

        // Causal mask (only the last two tiles straddle the diagonal)
        if (kt * 32 + 31 > qt * 64) {
#pragma unroll
            for (int r = 0; r < 2; r++) {
                int qrow = qt * 64 + 2 * ty + r;
                float* ss = r ? s1 : s0;
#pragma unroll
                for (int c = 0; c < 4; c++) {
                    int kcol = kt * 32 + tx + 8 * c;
                    if (kcol > qrow) ss[c] = -1e30f;
                }
            }
        }

        // Online softmax (row stats shared across the 8 tx lanes via shuffles)
#pragma unroll
        for (int r = 0; r < 2; r++) {
            float* ss = r ? s1 : s0;
            float rmax = fmaxf(fmaxf(ss[0], ss[1]), fmaxf(ss[2], ss[3]));
            rmax = fmaxf(rmax, __shfl_xor_sync(0xffffffffu, rmax, 1));
            rmax = fmaxf(rmax, __shfl_xor_sync(0xffffffffu, rmax, 2));
            rmax = fmaxf(rmax, __shfl_xor_sync(0xffffffffu, rmax, 4));
            float mnew = fmaxf(m_[r], rmax);
            float alpha = __expf(m_[r] - mnew);
            float p0 = __expf(ss[0] - mnew);
            float p1 = __expf(ss[1] - mnew);
            float p2 = __expf(ss[2] - mnew);
            float p3 = __expf(ss[3] - mnew);
            float rs = p0 + p1 + p2 + p3;
            rs += __shfl_xor_sync(0xffffffffu, rs, 1);
            rs += __shfl_xor_sync(0xffffffffu, rs, 2);
            rs += __shfl_xor_sync(0xffffffffu, rs, 4);
            l_[r] = l_[r] * alpha + rs;
            m_[r] = mnew;
#pragma unroll
            for (int c = 0; c < 8; c++) acc[r][c] *= alpha;
            Ps[2 * ty + r][tx + 0]  = p0;
            Ps[2 * ty + r][tx + 8]  = p1;
            Ps[2 * ty + r][tx + 16] = p2;
            Ps[2 * ty + r][tx + 24] = p3;
        }
        __syncthreads();

        // O += P V  (V transposed in smem; vectorize over k)
#pragma unroll
        for (int k4 = 0; k4 < 32; k4 += 4) {
            float4 pr0 = *(float4*)&Ps[2 * ty + 0][k4];
            float4 pr1 = *(float4*)&Ps[2 * ty + 1][k4];
#pragma unroll
            for (int c = 0; c < 8; c++) {
                float4 v4 = *(float4*)&Vt[tx + 8 * c][k4];
                acc[0][c] += pr0.x * v4.x + pr0.y * v4.y + pr0.z * v4.z + pr0.w * v4.w;
                acc[1][c] += pr1.x * v4.x + pr1.y * v4.y + pr1.z * v4.z + pr1.w * v4.w;
            }
        }
        __syncthreads();
    }

    // Normalize and write to [B, T, C] so the proj GEMM reads row-major.
#pragma unroll
    for (int r = 0; r < 2; r++) {
        int qrow = qt * 64 + 2 * ty + r;
        float inv = 1.f / l_[r];
        float* op = g_ao + ((size_t)(b * NT + qrow)) * NC + h * ND;
#pragma unroll
        for (int c = 0; c < 8; c++)
            op[tx + 8 * c] = acc[r][c] * inv;
    }
}

// ---------------------------------------------------------------------------
extern "C" void kernel_launch(void* const* d_in, const int* in_sizes, int n_in,
                              void* d_out, int out_size) {
    (void)in_sizes; (void)n_in; (void)out_size;
    const float* x      = (const float*)d_in[0];  // [B,T,C] = [8192,1024]
    const float* w_qkv  = (const float*)d_in[1];  // [1024,3072]
    const float* w_proj = (const float*)d_in[2];  // [1024,1024]
    float* out = (float*)d_out;                   // [8192,1024]

    // 1) qkv = x @ w_qkv, scattered into head-major q/k/v (q pre-scaled)
    gemm_tf32<3072, 1024, 1, 0><<<dim3(24, 64), 256>>>(x, w_qkv, nullptr);
    // 2) causal flash attention -> g_ao [B,T,C]
    attn_kernel<<<dim3(32, 64), 256>>>();
    // 3) out = attn_out @ w_proj
    gemm_tf32<1024, 1024, 0, 1><<<dim3(8, 64), 256>>>(nullptr, w_proj, out);
}

// round 2
// speedup vs baseline: 2.2080x; 2.2080x over previous
#include <cuda_runtime.h>
#include <cuda_bf16.h>
#include <cstdint>
#include <cstddef>

// Problem constants
// B=4, T=2048, C=1024, H=16, D=64
#define NB 4
#define NT 2048
#define NC 1024
#define NH 16
#define ND 64

// Head-major scratch [B,H,T,D] for q,k,v; attention output in [B,T,C] for proj GEMM.
__device__ float g_q[(size_t)NB * NH * NT * ND];
__device__ float g_k[(size_t)NB * NH * NT * ND];
__device__ float g_v[(size_t)NB * NH * NT * ND];
__device__ float g_ao[(size_t)NB * NT * NC];

__device__ __forceinline__ float ftf32(float x) {
    unsigned u;
    asm("cvt.rna.tf32.f32 %0, %1;" : "=r"(u) : "f"(x));
    return __uint_as_float(u);
}

__device__ __forceinline__ void mma8(float* c, const unsigned* a, const unsigned* b) {
    asm volatile(
        "mma.sync.aligned.m16n8k8.row.col.f32.tf32.tf32.f32 "
        "{%0,%1,%2,%3}, {%4,%5,%6,%7}, {%8,%9}, {%0,%1,%2,%3};\n"
        : "+f"(c[0]), "+f"(c[1]), "+f"(c[2]), "+f"(c[3])
        : "r"(a[0]), "r"(a[1]), "r"(a[2]), "r"(a[3]), "r"(b[0]), "r"(b[1]));
}

// Scatter epilogue for the QKV GEMM: col in [0,3072) -> (s, h, d); row -> (b, t).
// q is pre-scaled by 1/sqrt(D) = 0.125.
__device__ __forceinline__ void scatter_qkv(int gm, int gc, float v) {
    int s = gc >> 10;
    int rem = gc & 1023;
    int h = rem >> 6;
    int d = rem & 63;
    int b = gm >> 11;
    int t = gm & 2047;
    size_t idx = (((size_t)(b * NH + h)) * NT + t) * ND + d;
    if (s == 0)      g_q[idx] = v * 0.125f;
    else if (s == 1) g_k[idx] = v;
    else             g_v[idx] = v;
}

// ---------------------------------------------------------------------------
// TF32 GEMM: C[M x N] = A[M x K] * B[K x N], both row-major fp32.
// Block tile 128x128, K-tile 16, double-buffered smem, 8 warps (2x4 warp grid),
// warp tile 64x32, mma m16n8k8.
// EPI: 0 = plain store to Cout, 1 = scatter into g_q/g_k/g_v.
// ASRC: 0 = A param, 1 = A is g_ao (attention output).
// ---------------------------------------------------------------------------
template <int N, int K, int EPI, int ASRC>
__global__ __launch_bounds__(256, 2)
void gemm_tf32(const float* __restrict__ A, const float* __restrict__ Bm,
               float* __restrict__ Cout) {
    __shared__ float As[2][128][20];   // pitch 20: frag reads conflict-free
    __shared__ float Bs[2][16][136];   // pitch 136: frag reads conflict-free

    const int tid = threadIdx.x;
    const int lane = tid & 31, warp = tid >> 5;
    const int wm = warp & 1, wn = warp >> 1;
    const int quad = lane >> 2, qid = lane & 3;
    const int bm = blockIdx.y * 128, bn = blockIdx.x * 128;

    const float* Ap = ASRC ? (const float*)g_ao : A;

    // gmem load mapping
    const int ar = tid >> 1;            // A row within tile (0..127)
    const int ac = (tid & 1) * 8;       // A col base (0 or 8)
    const int br = tid >> 5;            // B row (0..7), also br+8
    const int bc = (tid & 31) * 4;      // B col base

    float acc[4][4][4];
#pragma unroll
    for (int i = 0; i < 4; i++)
#pragma unroll
        for (int j = 0; j < 4; j++)
#pragma unroll
            for (int k = 0; k < 4; k++) acc[i][j][k] = 0.f;

    float4 ra0, ra1, rb0, rb1;
    const int nk = K / 16;

#define LOADG(kt_)                                                             \
    {                                                                          \
        const float* ap_ = Ap + (size_t)(bm + ar) * K + (kt_) * 16 + ac;       \
        ra0 = *(const float4*)ap_;                                             \
        ra1 = *(const float4*)(ap_ + 4);                                       \
        const float* bp_ = Bm + (size_t)((kt_) * 16 + br) * N + bn + bc;       \
        rb0 = *(const float4*)bp_;                                             \
        rb1 = *(const float4*)(bp_ + (size_t)8 * N);                           \
    }

#define STORES(bb_)                                                            \
    {                                                                          \
        float* a0_ = &As[bb_][ar][ac];                                         \
        a0_[0] = ftf32(ra0.x); a0_[1] = ftf32(ra0.y);                          \
        a0_[2] = ftf32(ra0.z); a0_[3] = ftf32(ra0.w);                          \
        a0_[4] = ftf32(ra1.x); a0_[5] = ftf32(ra1.y);                          \
        a0_[6] = ftf32(ra1.z); a0_[7] = ftf32(ra1.w);                          \
        float* b0_ = &Bs[bb_][br][bc];                                         \
        b0_[0] = ftf32(rb0.x); b0_[1] = ftf32(rb0.y);                          \
        b0_[2] = ftf32(rb0.z); b0_[3] = ftf32(rb0.w);                          \
        float* b1_ = &Bs[bb_][br + 8][bc];                                     \
        b1_[0] = ftf32(rb1.x); b1_[1] = ftf32(rb1.y);                          \
        b1_[2] = ftf32(rb1.z); b1_[3] = ftf32(rb1.w);                          \
    }

    LOADG(0);
    STORES(0);
    __syncthreads();

    for (int kt = 0; kt < nk; kt++) {
        const int bb = kt & 1;
        const bool more = (kt + 1 < nk);
        if (more) LOADG(kt + 1);

#pragma unroll
        for (int kb = 0; kb < 16; kb += 8) {
            unsigned af[4][4], bf[4][2];
#pragma unroll
            for (int mt = 0; mt < 4; mt++) {
                int r = wm * 64 + mt * 16 + quad;
                af[mt][0] = __float_as_uint(As[bb][r][kb + qid]);
                af[mt][1] = __float_as_uint(As[bb][r + 8][kb + qid]);
                af[mt][2] = __float_as_uint(As[bb][r][kb + qid + 4]);
                af[mt][3] = __float_as_uint(As[bb][r + 8][kb + qid + 4]);
            }
#pragma unroll
            for (int nt = 0; nt < 4; nt++) {
                int cn = wn * 32 + nt * 8 + quad;
                bf[nt][0] = __float_as_uint(Bs[bb][kb + qid][cn]);
                bf[nt][1] = __float_as_uint(Bs[bb][kb + qid + 4][cn]);
            }
#pragma unroll
            for (int mt = 0; mt < 4; mt++)
#pragma unroll
                for (int nt = 0; nt < 4; nt++)
                    mma8(acc[mt][nt], af[mt], bf[nt]);
        }

        if (more) STORES(bb ^ 1);
        __syncthreads();
    }
#undef LOADG
#undef STORES

    // Epilogue
#pragma unroll
    for (int mt = 0; mt < 4; mt++) {
        int r0 = bm + wm * 64 + mt * 16 + quad;
#pragma unroll
        for (int nt = 0; nt < 4; nt++) {
            int c0 = bn + wn * 32 + nt * 8 + 2 * qid;
            float* cc = acc[mt][nt];
            if constexpr (EPI == 0) {
                Cout[(size_t)r0 * N + c0] = cc[0];
                Cout[(size_t)r0 * N + c0 + 1] = cc[1];
                Cout[(size_t)(r0 + 8) * N + c0] = cc[2];
                Cout[(size_t)(r0 + 8) * N + c0 + 1] = cc[3];
            } else {
                scatter_qkv(r0, c0, cc[0]);
                scatter_qkv(r0, c0 + 1, cc[1]);
                scatter_qkv(r0 + 8, c0, cc[2]);
                scatter_qkv(r0 + 8, c0 + 1, cc[3]);
            }
        }
    }
}

// ---------------------------------------------------------------------------
// Flash attention (causal, online softmax) on the TENSOR pipe (tf32 mma).
// Block: 128 threads (4 warps). q-tile 64 rows (16 per warp), k-tile 64 keys.
// Grid: (T/64 = 32, B*H = 64). Causal: only kt <= qt tiles.
//
// S = Q K^T via mma.m16n8k8 with Q split into tf32 (hi, lo) pair for accuracy
// (2 MMAs per step -> S error bounded by K's tf32 rounding only).
// Softmax is done in the MMA accumulator layout; row stats via shfl over the
// 4 quad lanes. P goes through smem (per-warp private rows -> __syncwarp only)
// to convert acc layout -> A-fragment layout for the PV MMA.
//
// Smem pitches (conflict-free by construction):
//   pitch 68 (= 4 mod 32): A-frag reads (row=lane>>2, col=lane&3) and
//                          QK^T B-frag reads (row=key=lane>>2, col=d=lane&3)
//   pitch 72 (= 8 mod 32): PV B-frag reads (row=key=lane&3, col=d=lane>>2)
// ---------------------------------------------------------------------------
__global__ __launch_bounds__(128)
void attn_mma() {
    extern __shared__ float sm[];
    float (*Qh)[68] = (float(*)[68])(sm);            // 64x68
    float (*Ql)[68] = (float(*)[68])(sm + 4352);     // 64x68
    float (*Ks)[68] = (float(*)[68])(sm + 8704);     // 64x68
    float (*Vs)[72] = (float(*)[72])(sm + 13056);    // 64x72
    float (*Ps)[68] = (float(*)[68])(sm + 17664);    // 64x68  (total 88064 B)

    const int qt = blockIdx.x;      // q tile (0..31)
    const int bh = blockIdx.y;      // b*H + h
    const int b = bh >> 4, h = bh & 15;

    const int tid = threadIdx.x;
    const int lane = tid & 31, warp = tid >> 5;
    const int g = lane >> 2, q4 = lane & 3;

    const float* Qg = g_q + ((size_t)bh * NT + (size_t)qt * 64) * ND;
    const float* Kg = g_k + (size_t)bh * NT * ND;
    const float* Vg = g_v + (size_t)bh * NT * ND;

    // Load Q tile, split into tf32 hi/lo
#pragma unroll
    for (int i = 0; i < 8; i++) {
        int idx = tid + i * 128;
        int r = idx >> 4, c = (idx & 15) * 4;
        float4 qv = *(const float4*)&Qg[r * 64 + c];
        float h0 = ftf32(qv.x), h1 = ftf32(qv.y), h2 = ftf32(qv.z), h3 = ftf32(qv.w);
        Qh[r][c + 0] = h0; Qh[r][c + 1] = h1; Qh[r][c + 2] = h2; Qh[r][c + 3] = h3;
        Ql[r][c + 0] = ftf32(qv.x - h0);
        Ql[r][c + 1] = ftf32(qv.y - h1);
        Ql[r][c + 2] = ftf32(qv.z - h2);
        Ql[r][c + 3] = ftf32(qv.w - h3);
    }

    const int row_lo = warp * 16 + g;       // local q row for c0/c1
    const int row_hi = row_lo + 8;          // local q row for c2/c3
    const int grow_lo = qt * 64 + row_lo;   // global q rows (for mask)
    const int grow_hi = grow_lo + 8;

    float m0 = -1e30f, m1 = -1e30f, l0 = 0.f, l1 = 0.f;
    float oacc[8][4];
#pragma unroll
    for (int nt = 0; nt < 8; nt++)
#pragma unroll
        for (int j = 0; j < 4; j++) oacc[nt][j] = 0.f;

    for (int kt = 0; kt <= qt; kt++) {
        __syncthreads();   // all warps done with previous Ks/Vs (and Q ready on kt=0)
        const float* kp = Kg + (size_t)kt * 64 * 64;
        const float* vp = Vg + (size_t)kt * 64 * 64;
#pragma unroll
        for (int i = 0; i < 8; i++) {
            int idx = tid + i * 128;
            int r = idx >> 4, c = (idx & 15) * 4;
            float4 kv = *(const float4*)&kp[r * 64 + c];
            Ks[r][c + 0] = ftf32(kv.x); Ks[r][c + 1] = ftf32(kv.y);
            Ks[r][c + 2] = ftf32(kv.z); Ks[r][c + 3] = ftf32(kv.w);
            float4 vv = *(const float4*)&vp[r * 64 + c];
            Vs[r][c + 0] = ftf32(vv.x); Vs[r][c + 1] = ftf32(vv.y);
            Vs[r][c + 2] = ftf32(vv.z); Vs[r][c + 3] = ftf32(vv.w);
        }
        __syncthreads();

        // ---- S = Q K^T (split-precision: hi + lo) ----
        float sacc[8][4];
#pragma unroll
        for (int nt = 0; nt < 8; nt++)
#pragma unroll
            for (int j = 0; j < 4; j++) sacc[nt][j] = 0.f;

#pragma unroll
        for (int kb = 0; kb < 64; kb += 8) {
            unsigned ah[4], al[4];
            ah[0] = __float_as_uint(Qh[row_lo][kb + q4]);
            ah[1] = __float_as_uint(Qh[row_hi][kb + q4]);
            ah[2] = __float_as_uint(Qh[row_lo][kb + q4 + 4]);
            ah[3] = __float_as_uint(Qh[row_hi][kb + q4 + 4]);
            al[0] = __float_as_uint(Ql[row_lo][kb + q4]);
            al[1] = __float_as_uint(Ql[row_hi][kb + q4]);
            al[2] = __float_as_uint(Ql[row_lo][kb + q4 + 4]);
            al[3] = __float_as_uint(Ql[row_hi][kb + q4 + 4]);
#pragma unroll
            for (int nt = 0; nt < 8; nt++) {
                unsigned bf[2];
                bf[0] = __float_as_uint(Ks[nt * 8 + g][kb + q4]);
                bf[1] = __float_as_uint(Ks[nt * 8 + g][kb + q4 + 4]);
                mma8(sacc[nt], ah, bf);
                mma8(sacc[nt], al, bf);
            }
        }

        // ---- causal mask (only diagonal tile) ----
        if (kt == qt) {
#pragma unroll
            for (int nt = 0; nt < 8; nt++) {
                int c0 = kt * 64 + nt * 8 + 2 * q4;
                if (c0 > grow_lo)     sacc[nt][0] = -1e30f;
                if (c0 + 1 > grow_lo) sacc[nt][1] = -1e30f;
                if (c0 > grow_hi)     sacc[nt][2] = -1e30f;
                if (c0 + 1 > grow_hi) sacc[nt][3] = -1e30f;
            }
        }

        // ---- online softmax (acc layout; stats over quad lanes) ----
        {
            float rmax = -1e30f;
#pragma unroll
            for (int nt = 0; nt < 8; nt++)
                rmax = fmaxf(rmax, fmaxf(sacc[nt][0], sacc[nt][1]));
            rmax = fmaxf(rmax, __shfl_xor_sync(0xffffffffu, rmax, 1));
            rmax = fmaxf(rmax, __shfl_xor_sync(0xffffffffu, rmax, 2));
            float mnew = fmaxf(m0, rmax);
            float alpha = __expf(m0 - mnew);
            float rs = 0.f;
#pragma unroll
            for (int nt = 0; nt < 8; nt++) {
                float p0 = __expf(sacc[nt][0] - mnew);
                float p1 = __expf(sacc[nt][1] - mnew);
                rs += p0 + p1;
                sacc[nt][0] = p0; sacc[nt][1] = p1;
            }
            rs += __shfl_xor_sync(0xffffffffu, rs, 1);
            rs += __shfl_xor_sync(0xffffffffu, rs, 2);
            l0 = l0 * alpha + rs;
            m0 = mnew;
#pragma unroll
            for (int nt = 0; nt < 8; nt++) { oacc[nt][0] *= alpha; oacc[nt][1] *= alpha; }
        }
        {
            float rmax = -1e30f;
#pragma unroll
            for (int nt = 0; nt < 8; nt++)
                rmax = fmaxf(rmax, fmaxf(sacc[nt][2], sacc[nt][3]));
            rmax = fmaxf(rmax, __shfl_xor_sync(0xffffffffu, rmax, 1));
            rmax = fmaxf(rmax, __shfl_xor_sync(0xffffffffu, rmax, 2));
            float mnew = fmaxf(m1, rmax);
            float alpha = __expf(m1 - mnew);
            float rs = 0.f;
#pragma unroll
            for (int nt = 0; nt < 8; nt++) {
                float p0 = __expf(sacc[nt][2] - mnew);
                float p1 = __expf(sacc[nt][3] - mnew);
                rs += p0 + p1;
                sacc[nt][2] = p0; sacc[nt][3] = p1;
            }
            rs += __shfl_xor_sync(0xffffffffu, rs, 1);
            rs += __shfl_xor_sync(0xffffffffu, rs, 2);
            l1 = l1 * alpha + rs;
            m1 = mnew;
#pragma unroll
            for (int nt = 0; nt < 8; nt++) { oacc[nt][2] *= alpha; oacc[nt][3] *= alpha; }
        }

        // ---- P: acc layout -> smem -> A-frag layout (warp-private rows) ----
#pragma unroll
        for (int nt = 0; nt < 8; nt++) {
            float2 plo = make_float2(ftf32(sacc[nt][0]), ftf32(sacc[nt][1]));
            float2 phi = make_float2(ftf32(sacc[nt][2]), ftf32(sacc[nt][3]));
            *(float2*)&Ps[row_lo][nt * 8 + 2 * q4] = plo;
            *(float2*)&Ps[row_hi][nt * 8 + 2 * q4] = phi;
        }
        __syncwarp();

        // ---- O += P V ----
#pragma unroll
        for (int kb = 0; kb < 64; kb += 8) {
            unsigned af[4];
            af[0] = __float_as_uint(Ps[row_lo][kb + q4]);
            af[1] = __float_as_uint(Ps[row_hi][kb + q4]);
            af[2] = __float_as_uint(Ps[row_lo][kb + q4 + 4]);
            af[3] = __float_as_uint(Ps[row_hi][kb + q4 + 4]);
#pragma unroll
            for (int nt = 0; nt < 8; nt++) {
                unsigned bf[2];
                bf[0] = __float_as_uint(Vs[kb + q4][nt * 8 + g]);
                bf[1] = __float_as_uint(Vs[kb + q4 + 4][nt * 8 + g]);
                mma8(oacc[nt], af, bf);
            }
        }
    }

    // ---- normalize and write to [B, T, C] ----
    float inv0 = 1.f / l0, inv1 = 1.f / l1;
    float* op_lo = g_ao + ((size_t)(b * NT + grow_lo)) * NC + h * ND;
    float* op_hi = g_ao + ((size_t)(b * NT + grow_hi)) * NC + h * ND;
#pragma unroll
    for (int nt = 0; nt < 8; nt++) {
        int c0 = nt * 8 + 2 * q4;
        *(float2*)&op_lo[c0] = make_float2(oacc[nt][0] * inv0, oacc[nt][1] * inv0);
        *(float2*)&op_hi[c0] = make_float2(oacc[nt][2] * inv1, oacc[nt][3] * inv1);
    }
}

// ---------------------------------------------------------------------------
extern "C" void kernel_launch(void* const* d_in, const int* in_sizes, int n_in,
                              void* d_out, int out_size) {
    (void)in_sizes; (void)n_in; (void)out_size;
    const float* x      = (const float*)d_in[0];  // [B,T,C] = [8192,1024]
    const float* w_qkv  = (const float*)d_in[1];  // [1024,3072]
    const float* w_proj = (const float*)d_in[2];  // [1024,1024]
    float* out = (float*)d_out;                   // [8192,1024]

    const int attn_smem = 88064;
    cudaFuncSetAttribute(attn_mma, cudaFuncAttributeMaxDynamicSharedMemorySize, attn_smem);

    // 1) qkv = x @ w_qkv, scattered into head-major q/k/v (q pre-scaled)
    gemm_tf32<3072, 1024, 1, 0><<<dim3(24, 64), 256>>>(x, w_qkv, nullptr);
    // 2) causal flash attention (tensor-pipe tf32) -> g_ao [B,T,C]
    attn_mma<<<dim3(32, 64), 128, attn_smem>>>();
    // 3) out = attn_out @ w_proj
    gemm_tf32<1024, 1024, 0, 1><<<dim3(8, 64), 256>>>(nullptr, w_proj, out);
}